// round 9
// baseline (speedup 1.0000x reference)
#include <cuda_runtime.h>

typedef unsigned long long ull;

// ---------------- packed f32x2 helpers (sm_103a FFMA2 path) ----------------
__device__ __forceinline__ ull f2pack(float lo, float hi) {
    ull r; asm("mov.b64 %0,{%1,%2};" : "=l"(r) : "f"(lo), "f"(hi)); return r;
}
__device__ __forceinline__ ull splat2(float v) { return f2pack(v, v); }
__device__ __forceinline__ ull ffma2(ull a, ull b, ull c) {
    ull d; asm("fma.rn.f32x2 %0,%1,%2,%3;" : "=l"(d) : "l"(a), "l"(b), "l"(c)); return d;
}
__device__ __forceinline__ float2 f2unpack(ull v) {
    float2 r; asm("mov.b64 {%0,%1},%2;" : "=f"(r.x), "=f"(r.y) : "l"(v)); return r;
}

// ---------------- scratch (device globals, no runtime allocation) ----------
__device__ float g_h1p[1024 * 32 * 196];      // stage-1 output, pooled (b,c,p14)
__device__ float g_h2 [1024 * 64 * 196];      // stage-2 output (b,c,p14) == flatten layout
__device__ float g_w2r [9 * 32 * 64];         // w2 reordered [k][c][co]
__device__ float g_ow2r[9 * 32 * 20];         // ow2 reordered [k][c][o(pad20)]
__device__ ull   g_fw1B[12544 * 128];         // fw1 transposed + splatted [k][n]
__device__ float g_fc1part[16 * 1024 * 128];  // split-K partials
__device__ float g_h3 [1024 * 128];           // fc1 output

// ---------------- prep kernels --------------------------------------------
__global__ void prep_w2r(const float* __restrict__ w2) {
    int id = blockIdx.x * blockDim.x + threadIdx.x;       // 9*32*64 = 18432
    if (id >= 9 * 32 * 64) return;
    int co = id % 64; int c = (id / 64) % 32; int k = id / (64 * 32);
    g_w2r[(k * 32 + c) * 64 + co] = w2[(co * 32 + c) * 9 + k];
}

__global__ void prep_ow2r(const float* __restrict__ ow2) {
    int id = blockIdx.x * blockDim.x + threadIdx.x;       // 9*32*20 = 5760
    if (id >= 9 * 32 * 20) return;
    int o = id % 20; int c = (id / 20) % 32; int k = id / (20 * 32);
    g_ow2r[(k * 32 + c) * 20 + o] = (o < 18) ? ow2[(o * 32 + c) * 9 + k] : 0.0f;
}

// tiled transpose + splat: fw1 [128][12544] -> g_fw1B ull [12544][128]
__global__ void prep_fw1B(const float* __restrict__ fw1) {
    __shared__ float tile[32][33];
    int k = blockIdx.x * 32 + threadIdx.x;
    int n = blockIdx.y * 32 + threadIdx.y;
    tile[threadIdx.y][threadIdx.x] = fw1[n * 12544 + k];
    __syncthreads();
    int k2 = blockIdx.x * 32 + threadIdx.y;
    int n2 = blockIdx.y * 32 + threadIdx.x;
    g_fw1B[k2 * 128 + n2] = splat2(tile[threadIdx.x][threadIdx.y]);
}

// ---------------- stage 1: conv1(offsets) + deform1 + relu + pool2x2 ------
__device__ __forceinline__ float samp28(const float* sx, int y, int x) {
    return (y >= 0 && y < 28 && x >= 0 && x < 28) ? sx[y * 28 + x] : 0.0f;
}

__global__ __launch_bounds__(784) void kA(
    const float* __restrict__ x,  const float* __restrict__ ow1,
    const float* __restrict__ ob1, const float* __restrict__ w1,
    const float* __restrict__ b1)
{
    __shared__ __align__(16) float sx[784];
    __shared__ __align__(16) float ss[9 * 784];    // bilinear samples [k][p28]
    __shared__ __align__(16) float sow1T[162];     // [k][o]
    __shared__ __align__(16) float sw1T[288];      // [k][c]
    __shared__ __align__(16) float sob1[18];
    __shared__ __align__(16) float sb1[32];
    int b = blockIdx.x, t = threadIdx.x;

    sx[t] = x[b * 784 + t];
    if (t < 162) { int o = t % 18, k = t / 18; sow1T[t] = ow1[o * 9 + k]; }
    if (t < 288) { int c = t % 32, k = t / 32; sw1T[t] = w1[c * 9 + k]; }
    if (t < 18) sob1[t] = ob1[t];
    if (t < 32) sb1[t] = b1[t];
    __syncthreads();

    // phase 1: one thread per 28x28 pixel — offset conv (1->18) + bilinear
    {
        int y = t / 28, xx = t % 28;
        ull off9[9];
        const ull* bb = (const ull*)sob1;
#pragma unroll
        for (int j = 0; j < 9; j++) off9[j] = bb[j];
#pragma unroll
        for (int ky = 0; ky < 3; ky++)
#pragma unroll
            for (int kx = 0; kx < 3; kx++) {
                float xv = samp28(sx, y - 1 + ky, xx - 1 + kx);
                ull xs = splat2(xv);
                const ull* wp = (const ull*)sow1T + (ky * 3 + kx) * 9;
#pragma unroll
                for (int j = 0; j < 9; j++) off9[j] = ffma2(xs, wp[j], off9[j]);
            }
#pragma unroll
        for (int k = 0; k < 9; k++) {
            float2 d = f2unpack(off9[k]);
            float py = d.x + (float)(y  - 1 + k / 3);
            float px = d.y + (float)(xx - 1 + k % 3);
            float y0f = floorf(py), x0f = floorf(px);
            int y0 = (int)y0f, x0i = (int)x0f;
            float wy1 = py - y0f, wx1 = px - x0f;
            float wy0 = 1.0f - wy1, wx0 = 1.0f - wx1;
            float v00 = samp28(sx, y0,     x0i    );
            float v01 = samp28(sx, y0,     x0i + 1);
            float v10 = samp28(sx, y0 + 1, x0i    );
            float v11 = samp28(sx, y0 + 1, x0i + 1);
            ss[k * 784 + t] = v00 * wy0 * wx0 + v01 * wy0 * wx1
                            + v10 * wy1 * wx0 + v11 * wy1 * wx1;
        }
    }
    __syncthreads();

    // phase 2: 4 groups x 8 channels, relu + 2x2 pool
    {
        int p = t % 196, g = t / 196;
        int oy = p / 14, ox = p % 14;
        float pool[8];
#pragma unroll
        for (int j = 0; j < 8; j++) pool[j] = 0.0f;
        const ull* bp = (const ull*)(sb1 + g * 8);
#pragma unroll
        for (int sub = 0; sub < 4; sub++) {
            int yy = oy * 2 + (sub >> 1);
            int xx = ox * 2 + (sub & 1);
            int pp = yy * 28 + xx;
            ull o4[4];
#pragma unroll
            for (int j = 0; j < 4; j++) o4[j] = bp[j];
#pragma unroll
            for (int k = 0; k < 9; k++) {
                ull vs = splat2(ss[k * 784 + pp]);
                const ull* wp = (const ull*)sw1T + k * 16 + g * 4;
                o4[0] = ffma2(vs, wp[0], o4[0]);
                o4[1] = ffma2(vs, wp[1], o4[1]);
                o4[2] = ffma2(vs, wp[2], o4[2]);
                o4[3] = ffma2(vs, wp[3], o4[3]);
            }
#pragma unroll
            for (int j = 0; j < 4; j++) {
                float2 u = f2unpack(o4[j]);
                pool[2 * j]     += fmaxf(u.x, 0.0f);
                pool[2 * j + 1] += fmaxf(u.y, 0.0f);
            }
        }
#pragma unroll
        for (int j = 0; j < 8; j++)
            g_h1p[(b * 32 + g * 8 + j) * 196 + p] = pool[j] * 0.25f;
    }
}

// ---------------- stage 2: conv2(offsets) + deform2 + relu -----------------
// 784 threads. Phase 2': 196 threads do the FULL offset conv (no partials,
// no reduction). Phase 4: 4 groups x 16 output channels, double-buffered
// gather buffer, 1 sync per k.
// dyn smem floats: sh[6272] | sv0[6272] | sv1[6272 (ow2r overlay)] |
//                  sw2[18432] | scoef[7056] | sidx[1764]  = 46068 (184.3KB)
__global__ __launch_bounds__(784) void kB(
    const float* __restrict__ ob2, const float* __restrict__ b2)
{
    extern __shared__ float smem[];
    float*    sh    = smem;             // 32*196 activations [c][p]
    float*    sv0   = smem + 6272;      // gather buf A
    float*    sv1   = smem + 12544;     // ow2r (phase 2') / gather buf B
    float*    sw2   = smem + 18816;     // w2r [k][c][co] (18432)
    float*    scoef = smem + 37248;     // bilinear coefs [k*4+q][196]
    unsigned* sidx  = (unsigned*)(smem + 44304);  // packed tap indices [k][196]
    __shared__ __align__(16) float sob2s[18];
    __shared__ __align__(16) float sb2s[64];

    int b = blockIdx.x, t = threadIdx.x;
    {   // vectorized load phase
        const float4* hsrc = (const float4*)(g_h1p + b * 6272);
        for (int i = t; i < 1568; i += 784) ((float4*)sh)[i] = hsrc[i];
        for (int i = t; i < 1440; i += 784) ((float4*)sv1)[i] = ((const float4*)g_ow2r)[i];
        for (int i = t; i < 4608; i += 784) ((float4*)sw2)[i] = ((const float4*)g_w2r)[i];
        if (t < 18) sob2s[t] = ob2[t];
        if (t < 64) sb2s[t]  = b2[t];
    }
    __syncthreads();

    int g = t / 196, p = t % 196;

    // phase 2': threads 0..195 — full offset conv (32 ch) + coefs + indices
    if (t < 196) {
        int y = p / 14, x = p % 14;
        ull a9[9];
        const ull* bb = (const ull*)sob2s;
#pragma unroll
        for (int j = 0; j < 9; j++) a9[j] = bb[j];
#pragma unroll
        for (int ky = 0; ky < 3; ky++)
#pragma unroll
            for (int kx = 0; kx < 3; kx++) {
                int yy = y - 1 + ky, xc = x - 1 + kx;
                if (yy >= 0 && yy < 14 && xc >= 0 && xc < 14) {
                    int p2 = yy * 14 + xc, kk = ky * 3 + kx;
                    const ull* ow = (const ull*)sv1 + (kk * 32) * 10;
#pragma unroll 8
                    for (int c = 0; c < 32; c++) {
                        ull hs = splat2(sh[c * 196 + p2]);
                        const ull* wp = ow + c * 10;
#pragma unroll
                        for (int j = 0; j < 9; j++) a9[j] = ffma2(hs, wp[j], a9[j]);
                    }
                }
            }
#pragma unroll
        for (int k = 0; k < 9; k++) {
            float2 d = f2unpack(a9[k]);
            float py = d.x + (float)(y - 1 + k / 3);
            float px = d.y + (float)(x - 1 + k % 3);
            float y0f = floorf(py), x0f = floorf(px);
            int y0 = (int)y0f, x0i = (int)x0f;
            float wy1 = py - y0f, wx1 = px - x0f;
            float wy0 = 1.0f - wy1, wx0 = 1.0f - wx1;
            bool by0 = (y0 >= 0) && (y0 < 14);
            bool by1 = (y0 + 1 >= 0) && (y0 + 1 < 14);
            bool bx0 = (x0i >= 0) && (x0i < 14);
            bool bx1 = (x0i + 1 >= 0) && (x0i + 1 < 14);
            float c00 = (by0 && bx0) ? wy0 * wx0 : 0.0f;
            float c01 = (by0 && bx1) ? wy0 * wx1 : 0.0f;
            float c10 = (by1 && bx0) ? wy1 * wx0 : 0.0f;
            float c11 = (by1 && bx1) ? wy1 * wx1 : 0.0f;
            unsigned i00 = (by0 && bx0) ? (unsigned)(y0 * 14 + x0i)           : 0u;
            unsigned i01 = (by0 && bx1) ? (unsigned)(y0 * 14 + x0i + 1)       : 0u;
            unsigned i10 = (by1 && bx0) ? (unsigned)((y0 + 1) * 14 + x0i)     : 0u;
            unsigned i11 = (by1 && bx1) ? (unsigned)((y0 + 1) * 14 + x0i + 1) : 0u;
            scoef[(k * 4 + 0) * 196 + p] = c00;
            scoef[(k * 4 + 1) * 196 + p] = c01;
            scoef[(k * 4 + 2) * 196 + p] = c10;
            scoef[(k * 4 + 3) * 196 + p] = c11;
            sidx[k * 196 + p] = i00 | (i01 << 8) | (i10 << 16) | (i11 << 24);
        }
    }
    __syncthreads();

    // phase 4: per-k gather into alternating buffer, one sync per k
    ull acc[8];
    {
        const ull* bp = (const ull*)(sb2s + g * 16);
#pragma unroll
        for (int j = 0; j < 8; j++) acc[j] = bp[j];
    }
#pragma unroll
    for (int k = 0; k < 9; k++) {
        float* buf = (k & 1) ? sv1 : sv0;
        unsigned ip = sidx[k * 196 + p];
        float c0 = scoef[(k * 4 + 0) * 196 + p];
        float c1 = scoef[(k * 4 + 1) * 196 + p];
        float c2 = scoef[(k * 4 + 2) * 196 + p];
        float c3 = scoef[(k * 4 + 3) * 196 + p];
        int i00 = ip & 255, i01 = (ip >> 8) & 255;
        int i10 = (ip >> 16) & 255, i11 = ip >> 24;
#pragma unroll
        for (int j = 0; j < 8; j++) {
            const float* base = sh + (g * 8 + j) * 196;
            buf[(g * 8 + j) * 196 + p] =
                c0 * base[i00] + c1 * base[i01] + c2 * base[i10] + c3 * base[i11];
        }
        __syncthreads();
        const float* wk = sw2 + k * 2048 + g * 16;
#pragma unroll 4
        for (int c = 0; c < 32; c++) {
            ull vs = splat2(buf[c * 196 + p]);
            const ulonglong2* wp = (const ulonglong2*)(wk + c * 64);
            ulonglong2 wa = wp[0], wb = wp[1], wc = wp[2], wd = wp[3];
            acc[0] = ffma2(vs, wa.x, acc[0]); acc[1] = ffma2(vs, wa.y, acc[1]);
            acc[2] = ffma2(vs, wb.x, acc[2]); acc[3] = ffma2(vs, wb.y, acc[3]);
            acc[4] = ffma2(vs, wc.x, acc[4]); acc[5] = ffma2(vs, wc.y, acc[5]);
            acc[6] = ffma2(vs, wd.x, acc[6]); acc[7] = ffma2(vs, wd.y, acc[7]);
        }
        // no trailing sync: next k writes the OTHER buffer; the buffer written
        // two iterations later is protected by the intervening sync.
    }
#pragma unroll
    for (int j = 0; j < 8; j++) {
        float2 u = f2unpack(acc[j]);
        g_h2[(b * 64 + g * 16 + 2 * j    ) * 196 + p] = fmaxf(u.x, 0.0f);
        g_h2[(b * 64 + g * 16 + 2 * j + 1) * 196 + p] = fmaxf(u.y, 0.0f);
    }
}

// ---------------- FC1: split-K GEMM (M=1024, N=128, K=12544) ---------------
// BM=64, BN=128, BK=16, splitK=16, 256 threads/block.
// Double-buffered smem stages + register prefetch: one sync per iteration,
// LDG latency hidden behind the FFMA2 window. B is pre-splatted (g_fw1B).
__global__ __launch_bounds__(256) void kC_gemm() {
    __shared__ __align__(16) float As[2][16][64];
    __shared__ __align__(16) ull   Bs[2][16][128];
    int tid = threadIdx.x;
    int m0 = blockIdx.x * 64;
    int kbase = blockIdx.y * 784;

    ull acc[4][4];
#pragma unroll
    for (int i = 0; i < 4; i++)
#pragma unroll
        for (int j = 0; j < 4; j++) acc[i][j] = 0ull;

    int ar  = tid / 4;            // A row 0..63
    int ac  = (tid % 4) * 4;      // A k-quad
    int brr = tid / 16;           // B k-row 0..15
    int bn  = (tid % 16) * 8;     // B n-octet base
    int m_base = (tid >> 5) * 8;  // 0..56
    int n_base = (tid & 31) * 4;  // 0..124

    const float* Ag = g_h2 + (m0 + ar) * 12544 + kbase + ac;
    const ull*   Bg = g_fw1B + (kbase + brr) * 128 + bn;

    // preload tile 0
    float4 av = *(const float4*)Ag;
    ulonglong2 bv0 = *(const ulonglong2*)(Bg);
    ulonglong2 bv1 = *(const ulonglong2*)(Bg + 2);
    ulonglong2 bv2 = *(const ulonglong2*)(Bg + 4);
    ulonglong2 bv3 = *(const ulonglong2*)(Bg + 6);
    As[0][ac + 0][ar] = av.x; As[0][ac + 1][ar] = av.y;
    As[0][ac + 2][ar] = av.z; As[0][ac + 3][ar] = av.w;
    *(ulonglong2*)(&Bs[0][brr][bn])     = bv0;
    *(ulonglong2*)(&Bs[0][brr][bn + 2]) = bv1;
    *(ulonglong2*)(&Bs[0][brr][bn + 4]) = bv2;
    *(ulonglong2*)(&Bs[0][brr][bn + 6]) = bv3;
    __syncthreads();

    for (int it = 0; it < 49; it++) {
        int cur = it & 1, nxt = cur ^ 1;
        bool more = (it + 1) < 49;
        if (more) {   // issue prefetch LDGs early; latency overlaps compute
            const float* ag = Ag + (it + 1) * 16;
            const ull*   bg = Bg + (it + 1) * 16 * 128;
            av  = *(const float4*)ag;
            bv0 = *(const ulonglong2*)(bg);
            bv1 = *(const ulonglong2*)(bg + 2);
            bv2 = *(const ulonglong2*)(bg + 4);
            bv3 = *(const ulonglong2*)(bg + 6);
        }
#pragma unroll
        for (int k = 0; k < 16; k++) {
            ulonglong2 a01 = *(const ulonglong2*)(&As[cur][k][m_base]);
            ulonglong2 a23 = *(const ulonglong2*)(&As[cur][k][m_base + 4]);
            ulonglong2 b01 = *(const ulonglong2*)(&Bs[cur][k][n_base]);
            ulonglong2 b23 = *(const ulonglong2*)(&Bs[cur][k][n_base + 2]);
            acc[0][0] = ffma2(a01.x, b01.x, acc[0][0]);
            acc[0][1] = ffma2(a01.x, b01.y, acc[0][1]);
            acc[0][2] = ffma2(a01.x, b23.x, acc[0][2]);
            acc[0][3] = ffma2(a01.x, b23.y, acc[0][3]);
            acc[1][0] = ffma2(a01.y, b01.x, acc[1][0]);
            acc[1][1] = ffma2(a01.y, b01.y, acc[1][1]);
            acc[1][2] = ffma2(a01.y, b23.x, acc[1][2]);
            acc[1][3] = ffma2(a01.y, b23.y, acc[1][3]);
            acc[2][0] = ffma2(a23.x, b01.x, acc[2][0]);
            acc[2][1] = ffma2(a23.x, b01.y, acc[2][1]);
            acc[2][2] = ffma2(a23.x, b23.x, acc[2][2]);
            acc[2][3] = ffma2(a23.x, b23.y, acc[2][3]);
            acc[3][0] = ffma2(a23.y, b01.x, acc[3][0]);
            acc[3][1] = ffma2(a23.y, b01.y, acc[3][1]);
            acc[3][2] = ffma2(a23.y, b23.x, acc[3][2]);
            acc[3][3] = ffma2(a23.y, b23.y, acc[3][3]);
        }
        if (more) {
            As[nxt][ac + 0][ar] = av.x; As[nxt][ac + 1][ar] = av.y;
            As[nxt][ac + 2][ar] = av.z; As[nxt][ac + 3][ar] = av.w;
            *(ulonglong2*)(&Bs[nxt][brr][bn])     = bv0;
            *(ulonglong2*)(&Bs[nxt][brr][bn + 2]) = bv1;
            *(ulonglong2*)(&Bs[nxt][brr][bn + 4]) = bv2;
            *(ulonglong2*)(&Bs[nxt][brr][bn + 6]) = bv3;
        }
        __syncthreads();
    }
    float* dst = g_fc1part + blockIdx.y * 131072;
#pragma unroll
    for (int mp = 0; mp < 4; mp++) {
        int r0 = (m0 + m_base + 2 * mp) * 128 + n_base;
#pragma unroll
        for (int j = 0; j < 4; j++) {
            float2 u = f2unpack(acc[mp][j]);
            dst[r0 + j]       = u.x;
            dst[r0 + 128 + j] = u.y;
        }
    }
}

__global__ void kE_reduce(const float* __restrict__ fb1) {
    int id = blockIdx.x * blockDim.x + threadIdx.x;  // 131072
    if (id >= 131072) return;
    int n = id % 128;
    float s = fb1[n];
#pragma unroll
    for (int zz = 0; zz < 16; zz++) s += g_fc1part[zz * 131072 + id];
    g_h3[id] = fmaxf(s, 0.0f);
}

// ---------------- FC2 ------------------------------------------------------
__global__ void kF_fc2(const float* __restrict__ fw2, const float* __restrict__ fb2,
                       float* __restrict__ out) {
    int id = blockIdx.x * blockDim.x + threadIdx.x;  // 10240
    if (id >= 10240) return;
    int m = id / 10, n = id % 10;
    float s = fb2[n];
    const float* hrow = g_h3 + m * 128;
    const float* wrow = fw2 + n * 128;
#pragma unroll 8
    for (int j = 0; j < 128; j++) s += hrow[j] * wrow[j];
    out[id] = s;
}

// ---------------- launch ---------------------------------------------------
extern "C" void kernel_launch(void* const* d_in, const int* in_sizes, int n_in,
                              void* d_out, int out_size) {
    const float* x   = (const float*)d_in[0];
    const float* ow1 = (const float*)d_in[1];
    const float* ob1 = (const float*)d_in[2];
    const float* w1  = (const float*)d_in[3];
    const float* b1  = (const float*)d_in[4];
    const float* ow2 = (const float*)d_in[5];
    const float* ob2 = (const float*)d_in[6];
    const float* w2  = (const float*)d_in[7];
    const float* b2  = (const float*)d_in[8];
    const float* fw1 = (const float*)d_in[9];
    const float* fb1 = (const float*)d_in[10];
    const float* fw2 = (const float*)d_in[11];
    const float* fb2 = (const float*)d_in[12];
    float* out = (float*)d_out;

    prep_w2r <<<(18432 + 255) / 256, 256>>>(w2);
    prep_ow2r<<<(5760  + 255) / 256, 256>>>(ow2);
    {
        dim3 tg(392, 4);
        dim3 tb(32, 32);
        prep_fw1B<<<tg, tb>>>(fw1);
    }

    kA<<<1024, 784>>>(x, ow1, ob1, w1, b1);

    const int KB_SMEM = 46068 * 4;   // 184272 bytes
    cudaFuncSetAttribute(kB, cudaFuncAttributeMaxDynamicSharedMemorySize, KB_SMEM);
    kB<<<1024, 784, KB_SMEM>>>(ob2, b2);

    dim3 gg(16, 16);
    kC_gemm<<<gg, 256>>>();
    kE_reduce<<<(131072 + 255) / 256, 256>>>(fb1);
    kF_fc2<<<(10240 + 255) / 256, 256>>>(fw2, fb2, out);
}

// round 10
// speedup vs baseline: 1.7706x; 1.7706x over previous
#include <cuda_runtime.h>

typedef unsigned long long ull;

// ---------------- packed f32x2 helpers (sm_103a FFMA2 path) ----------------
__device__ __forceinline__ ull f2pack(float lo, float hi) {
    ull r; asm("mov.b64 %0,{%1,%2};" : "=l"(r) : "f"(lo), "f"(hi)); return r;
}
__device__ __forceinline__ ull splat2(float v) { return f2pack(v, v); }
__device__ __forceinline__ ull ffma2(ull a, ull b, ull c) {
    ull d; asm("fma.rn.f32x2 %0,%1,%2,%3;" : "=l"(d) : "l"(a), "l"(b), "l"(c)); return d;
}
__device__ __forceinline__ float2 f2unpack(ull v) {
    float2 r; asm("mov.b64 {%0,%1},%2;" : "=f"(r.x), "=f"(r.y) : "l"(v)); return r;
}

// ---------------- scratch (device globals, no runtime allocation) ----------
__device__ float g_h1p[1024 * 32 * 196];      // stage-1 output, pooled (b,c,p14)
__device__ float g_h2 [1024 * 64 * 196];      // stage-2 output (b,c,p14) == flatten layout
__device__ float g_w2r [9 * 32 * 64];         // w2 reordered [k][c][co]
__device__ float g_ow2r[9 * 32 * 20];         // ow2 reordered [k][c][o(pad20)]
__device__ float g_fw1T[12544 * 128];         // fw1 transposed [k][n]
__device__ float g_fc1part[16 * 1024 * 128];  // split-K partials
__device__ float g_h3 [1024 * 128];           // fc1 output

// ---------------- prep kernels --------------------------------------------
__global__ void prep_w2r(const float* __restrict__ w2) {
    int id = blockIdx.x * blockDim.x + threadIdx.x;       // 9*32*64 = 18432
    if (id >= 9 * 32 * 64) return;
    int co = id % 64; int c = (id / 64) % 32; int k = id / (64 * 32);
    g_w2r[(k * 32 + c) * 64 + co] = w2[(co * 32 + c) * 9 + k];
}

__global__ void prep_ow2r(const float* __restrict__ ow2) {
    int id = blockIdx.x * blockDim.x + threadIdx.x;       // 9*32*20 = 5760
    if (id >= 9 * 32 * 20) return;
    int o = id % 20; int c = (id / 20) % 32; int k = id / (20 * 32);
    g_ow2r[(k * 32 + c) * 20 + o] = (o < 18) ? ow2[(o * 32 + c) * 9 + k] : 0.0f;
}

// tiled transpose: fw1 [128][12544] -> g_fw1T [12544][128], both sides coalesced
__global__ void prep_fw1T(const float* __restrict__ fw1) {
    __shared__ float tile[32][33];
    int k = blockIdx.x * 32 + threadIdx.x;
    int n = blockIdx.y * 32 + threadIdx.y;
    tile[threadIdx.y][threadIdx.x] = fw1[n * 12544 + k];
    __syncthreads();
    int k2 = blockIdx.x * 32 + threadIdx.y;
    int n2 = blockIdx.y * 32 + threadIdx.x;
    g_fw1T[k2 * 128 + n2] = tile[threadIdx.x][threadIdx.y];
}

// ---------------- stage 1: conv1(offsets) + deform1 + relu + pool2x2 ------
__device__ __forceinline__ float samp28(const float* sx, int y, int x) {
    return (y >= 0 && y < 28 && x >= 0 && x < 28) ? sx[y * 28 + x] : 0.0f;
}

__global__ __launch_bounds__(784) void kA(
    const float* __restrict__ x,  const float* __restrict__ ow1,
    const float* __restrict__ ob1, const float* __restrict__ w1,
    const float* __restrict__ b1)
{
    __shared__ __align__(16) float sx[784];
    __shared__ __align__(16) float ss[9 * 784];    // bilinear samples [k][p28]
    __shared__ __align__(16) float sow1T[162];     // [k][o]
    __shared__ __align__(16) float sw1T[288];      // [k][c]
    __shared__ __align__(16) float sob1[18];
    __shared__ __align__(16) float sb1[32];
    int b = blockIdx.x, t = threadIdx.x;

    sx[t] = x[b * 784 + t];
    if (t < 162) { int o = t % 18, k = t / 18; sow1T[t] = ow1[o * 9 + k]; }
    if (t < 288) { int c = t % 32, k = t / 32; sw1T[t] = w1[c * 9 + k]; }
    if (t < 18) sob1[t] = ob1[t];
    if (t < 32) sb1[t] = b1[t];
    __syncthreads();

    // phase 1: one thread per 28x28 pixel — offset conv (1->18) + bilinear
    {
        int y = t / 28, xx = t % 28;
        ull off9[9];
        const ull* bb = (const ull*)sob1;
#pragma unroll
        for (int j = 0; j < 9; j++) off9[j] = bb[j];
#pragma unroll
        for (int ky = 0; ky < 3; ky++)
#pragma unroll
            for (int kx = 0; kx < 3; kx++) {
                float xv = samp28(sx, y - 1 + ky, xx - 1 + kx);
                ull xs = splat2(xv);
                const ull* wp = (const ull*)sow1T + (ky * 3 + kx) * 9;
#pragma unroll
                for (int j = 0; j < 9; j++) off9[j] = ffma2(xs, wp[j], off9[j]);
            }
#pragma unroll
        for (int k = 0; k < 9; k++) {
            float2 d = f2unpack(off9[k]);
            float py = d.x + (float)(y  - 1 + k / 3);
            float px = d.y + (float)(xx - 1 + k % 3);
            float y0f = floorf(py), x0f = floorf(px);
            int y0 = (int)y0f, x0i = (int)x0f;
            float wy1 = py - y0f, wx1 = px - x0f;
            float wy0 = 1.0f - wy1, wx0 = 1.0f - wx1;
            float v00 = samp28(sx, y0,     x0i    );
            float v01 = samp28(sx, y0,     x0i + 1);
            float v10 = samp28(sx, y0 + 1, x0i    );
            float v11 = samp28(sx, y0 + 1, x0i + 1);
            ss[k * 784 + t] = v00 * wy0 * wx0 + v01 * wy0 * wx1
                            + v10 * wy1 * wx0 + v11 * wy1 * wx1;
        }
    }
    __syncthreads();

    // phase 2: 4 groups x 8 channels, relu + 2x2 pool
    {
        int p = t % 196, g = t / 196;
        int oy = p / 14, ox = p % 14;
        float pool[8];
#pragma unroll
        for (int j = 0; j < 8; j++) pool[j] = 0.0f;
        const ull* bp = (const ull*)(sb1 + g * 8);
#pragma unroll
        for (int sub = 0; sub < 4; sub++) {
            int yy = oy * 2 + (sub >> 1);
            int xx = ox * 2 + (sub & 1);
            int pp = yy * 28 + xx;
            ull o4[4];
#pragma unroll
            for (int j = 0; j < 4; j++) o4[j] = bp[j];
#pragma unroll
            for (int k = 0; k < 9; k++) {
                ull vs = splat2(ss[k * 784 + pp]);
                const ull* wp = (const ull*)sw1T + k * 16 + g * 4;
                o4[0] = ffma2(vs, wp[0], o4[0]);
                o4[1] = ffma2(vs, wp[1], o4[1]);
                o4[2] = ffma2(vs, wp[2], o4[2]);
                o4[3] = ffma2(vs, wp[3], o4[3]);
            }
#pragma unroll
            for (int j = 0; j < 4; j++) {
                float2 u = f2unpack(o4[j]);
                pool[2 * j]     += fmaxf(u.x, 0.0f);
                pool[2 * j + 1] += fmaxf(u.y, 0.0f);
            }
        }
#pragma unroll
        for (int j = 0; j < 8; j++)
            g_h1p[(b * 32 + g * 8 + j) * 196 + p] = pool[j] * 0.25f;
    }
}

// ---------------- stage 2: conv2(offsets) + deform2 + relu -----------------
// 784 threads: 4 groups x (16 output channels | 8 input-channel slice).
// dynamic smem: sh[6272] | sv[6272] (ow2r, then gather buffer) | sw2[18432] | sbuf[14112]
__global__ __launch_bounds__(784) void kB(
    const float* __restrict__ ob2, const float* __restrict__ b2)
{
    extern __shared__ float smem[];
    float*    sh   = smem;            // 32*196 activations [c][p]
    float*    sv   = smem + 6272;     // ow2r (phase 2), gather v[c][p] (phase 4)
    float*    sw2  = smem + 12544;    // w2r [k][c][co]
    float*    sbuf = smem + 30976;    // offset partials -> coefs
    unsigned* sidx = (unsigned*)(smem + 30976) + 7056;  // packed tap indices
    __shared__ __align__(16) float sob2s[18];
    __shared__ __align__(16) float sb2s[64];

    int b = blockIdx.x, t = threadIdx.x;
    for (int i = t; i < 6272;  i += 784) sh[i]  = g_h1p[b * 6272 + i];
    for (int i = t; i < 5760;  i += 784) sv[i]  = g_ow2r[i];
    for (int i = t; i < 18432; i += 784) sw2[i] = g_w2r[i];
    if (t < 18) sob2s[t] = ob2[t];
    if (t < 64) sb2s[t]  = b2[t];
    __syncthreads();

    int g = t / 196, p = t % 196;
    int y = p / 14,  x = p % 14;

    // phase 2: partial offset conv (each group covers 8 input channels)
    {
        ull a9[9];
        if (g == 0) {
            const ull* bb = (const ull*)sob2s;
#pragma unroll
            for (int j = 0; j < 9; j++) a9[j] = bb[j];
        } else {
#pragma unroll
            for (int j = 0; j < 9; j++) a9[j] = 0ull;
        }
#pragma unroll
        for (int ky = 0; ky < 3; ky++)
#pragma unroll
            for (int kx = 0; kx < 3; kx++) {
                int yy = y - 1 + ky, xc = x - 1 + kx;
                if (yy >= 0 && yy < 14 && xc >= 0 && xc < 14) {
                    int p2 = yy * 14 + xc, kk = ky * 3 + kx;
                    const float* shb = sh + g * 8 * 196 + p2;
                    const ull* ow = (const ull*)sv + (kk * 32 + g * 8) * 10;
#pragma unroll
                    for (int cj = 0; cj < 8; cj++) {
                        ull hs = splat2(shb[cj * 196]);
                        const ull* wp = ow + cj * 10;
#pragma unroll
                        for (int j = 0; j < 9; j++) a9[j] = ffma2(hs, wp[j], a9[j]);
                    }
                }
            }
        float* dst = sbuf + (g * 196 + p) * 18;
#pragma unroll
        for (int j = 0; j < 9; j++) {
            float2 u = f2unpack(a9[j]);
            dst[2 * j] = u.x; dst[2 * j + 1] = u.y;
        }
    }
    __syncthreads();

    // phase 3: reduce partials, compute bilinear coefs + packed indices
    float offv[18];
    if (t < 196) {
#pragma unroll
        for (int o = 0; o < 18; o++)
            offv[o] = sbuf[t * 18 + o] + sbuf[(196 + t) * 18 + o]
                    + sbuf[(392 + t) * 18 + o] + sbuf[(588 + t) * 18 + o];
    }
    __syncthreads();
    if (t < 196) {
#pragma unroll
        for (int k = 0; k < 9; k++) {
            float py = offv[2 * k]     + (float)(y - 1 + k / 3);
            float px = offv[2 * k + 1] + (float)(x - 1 + k % 3);
            float y0f = floorf(py), x0f = floorf(px);
            int y0 = (int)y0f, x0i = (int)x0f;
            float wy1 = py - y0f, wx1 = px - x0f;
            float wy0 = 1.0f - wy1, wx0 = 1.0f - wx1;
            bool by0 = (y0 >= 0) && (y0 < 14);
            bool by1 = (y0 + 1 >= 0) && (y0 + 1 < 14);
            bool bx0 = (x0i >= 0) && (x0i < 14);
            bool bx1 = (x0i + 1 >= 0) && (x0i + 1 < 14);
            float c00 = (by0 && bx0) ? wy0 * wx0 : 0.0f;
            float c01 = (by0 && bx1) ? wy0 * wx1 : 0.0f;
            float c10 = (by1 && bx0) ? wy1 * wx0 : 0.0f;
            float c11 = (by1 && bx1) ? wy1 * wx1 : 0.0f;
            unsigned i00 = (by0 && bx0) ? (unsigned)(y0 * 14 + x0i)           : 0u;
            unsigned i01 = (by0 && bx1) ? (unsigned)(y0 * 14 + x0i + 1)       : 0u;
            unsigned i10 = (by1 && bx0) ? (unsigned)((y0 + 1) * 14 + x0i)     : 0u;
            unsigned i11 = (by1 && bx1) ? (unsigned)((y0 + 1) * 14 + x0i + 1) : 0u;
            sbuf[(k * 4 + 0) * 196 + t] = c00;
            sbuf[(k * 4 + 1) * 196 + t] = c01;
            sbuf[(k * 4 + 2) * 196 + t] = c10;
            sbuf[(k * 4 + 3) * 196 + t] = c11;
            sidx[k * 196 + t] = i00 | (i01 << 8) | (i10 << 16) | (i11 << 24);
        }
    }
    __syncthreads();

    // phase 4: per-k shared gather, then 16-channel FFMA2 accumulation
    ull acc[8];
    {
        const ull* bp = (const ull*)(sb2s + g * 16);
#pragma unroll
        for (int j = 0; j < 8; j++) acc[j] = bp[j];
    }
    for (int k = 0; k < 9; k++) {
        unsigned ip = sidx[k * 196 + p];
        float c0 = sbuf[(k * 4 + 0) * 196 + p];
        float c1 = sbuf[(k * 4 + 1) * 196 + p];
        float c2 = sbuf[(k * 4 + 2) * 196 + p];
        float c3 = sbuf[(k * 4 + 3) * 196 + p];
        int i00 = ip & 255, i01 = (ip >> 8) & 255;
        int i10 = (ip >> 16) & 255, i11 = ip >> 24;
#pragma unroll
        for (int j = 0; j < 8; j++) {
            const float* base = sh + (g * 8 + j) * 196;
            sv[(g * 8 + j) * 196 + p] =
                c0 * base[i00] + c1 * base[i01] + c2 * base[i10] + c3 * base[i11];
        }
        __syncthreads();
        const float* wk = sw2 + k * 2048 + g * 16;
#pragma unroll 4
        for (int c = 0; c < 32; c++) {
            ull vs = splat2(sv[c * 196 + p]);
            const ulonglong2* wp = (const ulonglong2*)(wk + c * 64);
            ulonglong2 wa = wp[0], wb = wp[1], wc = wp[2], wd = wp[3];
            acc[0] = ffma2(vs, wa.x, acc[0]); acc[1] = ffma2(vs, wa.y, acc[1]);
            acc[2] = ffma2(vs, wb.x, acc[2]); acc[3] = ffma2(vs, wb.y, acc[3]);
            acc[4] = ffma2(vs, wc.x, acc[4]); acc[5] = ffma2(vs, wc.y, acc[5]);
            acc[6] = ffma2(vs, wd.x, acc[6]); acc[7] = ffma2(vs, wd.y, acc[7]);
        }
        __syncthreads();
    }
#pragma unroll
    for (int j = 0; j < 8; j++) {
        float2 u = f2unpack(acc[j]);
        g_h2[(b * 64 + g * 16 + 2 * j    ) * 196 + p] = fmaxf(u.x, 0.0f);
        g_h2[(b * 64 + g * 16 + 2 * j + 1) * 196 + p] = fmaxf(u.y, 0.0f);
    }
}

// ---------------- FC1: split-K GEMM (M=1024, N=128, K=12544) ---------------
// BM=32, BN=128, BK=16, splitK=16, 256 threads/block, thread tile 4x4 (FFMA2).
__global__ __launch_bounds__(256) void kC_gemm() {
    __shared__ __align__(16) float As[16][32];
    __shared__ __align__(16) float Bs[16][128];
    int tid = threadIdx.x;
    int m0 = blockIdx.x * 32;
    int z  = blockIdx.z;
    int kbase = z * 784;

    ull acc[4][2];
#pragma unroll
    for (int i = 0; i < 4; i++) { acc[i][0] = 0ull; acc[i][1] = 0ull; }

    int lm = tid / 8;            // A load: row within tile
    int lk = (tid % 8) * 2;      // A load: k pair
    int br = tid / 32;           // B load: row 0..7 (and +8)
    int bc = (tid % 32) * 4;     // B load: col quad
    int m_base = (tid >> 5) * 4;
    int n_base = (tid & 31) * 4;

    for (int it = 0; it < 49; it++) {
        int k0 = kbase + it * 16;
        const float* arow = g_h2 + (m0 + lm) * 12544 + k0 + lk;
        float a0 = arow[0], a1 = arow[1];
        As[lk][lm] = a0; As[lk + 1][lm] = a1;
        float4 b0 = *reinterpret_cast<const float4*>(&g_fw1T[(k0 + br) * 128 + bc]);
        float4 b1 = *reinterpret_cast<const float4*>(&g_fw1T[(k0 + br + 8) * 128 + bc]);
        *reinterpret_cast<float4*>(&Bs[br][bc]) = b0;
        *reinterpret_cast<float4*>(&Bs[br + 8][bc]) = b1;
        __syncthreads();
#pragma unroll
        for (int k = 0; k < 16; k++) {
            float4 av = *reinterpret_cast<const float4*>(&As[k][m_base]);
            ulonglong2 bv = *reinterpret_cast<const ulonglong2*>(&Bs[k][n_base]);
            ull s;
            s = splat2(av.x); acc[0][0] = ffma2(s, bv.x, acc[0][0]); acc[0][1] = ffma2(s, bv.y, acc[0][1]);
            s = splat2(av.y); acc[1][0] = ffma2(s, bv.x, acc[1][0]); acc[1][1] = ffma2(s, bv.y, acc[1][1]);
            s = splat2(av.z); acc[2][0] = ffma2(s, bv.x, acc[2][0]); acc[2][1] = ffma2(s, bv.y, acc[2][1]);
            s = splat2(av.w); acc[3][0] = ffma2(s, bv.x, acc[3][0]); acc[3][1] = ffma2(s, bv.y, acc[3][1]);
        }
        __syncthreads();
    }
#pragma unroll
    for (int i = 0; i < 4; i++) {
        float2 u0 = f2unpack(acc[i][0]);
        float2 u1 = f2unpack(acc[i][1]);
        float* dst = g_fc1part + z * 131072 + (m0 + m_base + i) * 128 + n_base;
        dst[0] = u0.x; dst[1] = u0.y; dst[2] = u1.x; dst[3] = u1.y;
    }
}

__global__ void kE_reduce(const float* __restrict__ fb1) {
    int id = blockIdx.x * blockDim.x + threadIdx.x;  // 131072
    if (id >= 131072) return;
    int n = id % 128;
    float s = fb1[n];
#pragma unroll
    for (int zz = 0; zz < 16; zz++) s += g_fc1part[zz * 131072 + id];
    g_h3[id] = fmaxf(s, 0.0f);
}

// ---------------- FC2 ------------------------------------------------------
__global__ void kF_fc2(const float* __restrict__ fw2, const float* __restrict__ fb2,
                       float* __restrict__ out) {
    int id = blockIdx.x * blockDim.x + threadIdx.x;  // 10240
    if (id >= 10240) return;
    int m = id / 10, n = id % 10;
    float s = fb2[n];
    const float* hrow = g_h3 + m * 128;
    const float* wrow = fw2 + n * 128;
#pragma unroll 8
    for (int j = 0; j < 128; j++) s += hrow[j] * wrow[j];
    out[id] = s;
}

// ---------------- launch ---------------------------------------------------
extern "C" void kernel_launch(void* const* d_in, const int* in_sizes, int n_in,
                              void* d_out, int out_size) {
    const float* x   = (const float*)d_in[0];
    const float* ow1 = (const float*)d_in[1];
    const float* ob1 = (const float*)d_in[2];
    const float* w1  = (const float*)d_in[3];
    const float* b1  = (const float*)d_in[4];
    const float* ow2 = (const float*)d_in[5];
    const float* ob2 = (const float*)d_in[6];
    const float* w2  = (const float*)d_in[7];
    const float* b2  = (const float*)d_in[8];
    const float* fw1 = (const float*)d_in[9];
    const float* fb1 = (const float*)d_in[10];
    const float* fw2 = (const float*)d_in[11];
    const float* fb2 = (const float*)d_in[12];
    float* out = (float*)d_out;

    prep_w2r <<<(18432 + 255) / 256, 256>>>(w2);
    prep_ow2r<<<(5760  + 255) / 256, 256>>>(ow2);
    {
        dim3 tg(392, 4);
        dim3 tb(32, 32);
        prep_fw1T<<<tg, tb>>>(fw1);
    }

    kA<<<1024, 784>>>(x, ow1, ob1, w1, b1);

    const int KB_SMEM = 45088 * 4;   // 180352 bytes
    cudaFuncSetAttribute(kB, cudaFuncAttributeMaxDynamicSharedMemorySize, KB_SMEM);
    kB<<<1024, 784, KB_SMEM>>>(ob2, b2);

    dim3 gg(32, 1, 16);
    kC_gemm<<<gg, 256>>>();
    kE_reduce<<<(131072 + 255) / 256, 256>>>(fb1);
    kF_fc2<<<(10240 + 255) / 256, 256>>>(fw2, fb2, out);
}

// round 12
// speedup vs baseline: 1.8132x; 1.0241x over previous
#include <cuda_runtime.h>

typedef unsigned long long ull;

// ---------------- packed f32x2 helpers (sm_103a FFMA2 path) ----------------
__device__ __forceinline__ ull f2pack(float lo, float hi) {
    ull r; asm("mov.b64 %0,{%1,%2};" : "=l"(r) : "f"(lo), "f"(hi)); return r;
}
__device__ __forceinline__ ull splat2(float v) { return f2pack(v, v); }
__device__ __forceinline__ ull ffma2(ull a, ull b, ull c) {
    ull d; asm("fma.rn.f32x2 %0,%1,%2,%3;" : "=l"(d) : "l"(a), "l"(b), "l"(c)); return d;
}
__device__ __forceinline__ float2 f2unpack(ull v) {
    float2 r; asm("mov.b64 {%0,%1},%2;" : "=f"(r.x), "=f"(r.y) : "l"(v)); return r;
}

// ---------------- scratch (device globals, no runtime allocation) ----------
__device__ float g_h1p[1024 * 32 * 196];      // stage-1 output, pooled (b,c,p14)
__device__ float g_h2 [1024 * 64 * 196];      // stage-2 output (b,c,p14) == flatten layout
__device__ float g_w2r [9 * 32 * 64];         // w2 reordered [k][c][co]
__device__ float g_ow2r[9 * 32 * 20];         // ow2 reordered [k][c][o(pad20)]
__device__ float g_fw1T[12544 * 128];         // fw1 transposed [k][n]
__device__ float g_fc1part[16 * 1024 * 128];  // split-K partials
__device__ float g_h3 [1024 * 128];           // fc1 output

// ---------------- prep kernels --------------------------------------------
__global__ void prep_w2r(const float* __restrict__ w2) {
    int id = blockIdx.x * blockDim.x + threadIdx.x;       // 9*32*64 = 18432
    if (id >= 9 * 32 * 64) return;
    int co = id % 64; int c = (id / 64) % 32; int k = id / (64 * 32);
    g_w2r[(k * 32 + c) * 64 + co] = w2[(co * 32 + c) * 9 + k];
}

__global__ void prep_ow2r(const float* __restrict__ ow2) {
    int id = blockIdx.x * blockDim.x + threadIdx.x;       // 9*32*20 = 5760
    if (id >= 9 * 32 * 20) return;
    int o = id % 20; int c = (id / 20) % 32; int k = id / (20 * 32);
    g_ow2r[(k * 32 + c) * 20 + o] = (o < 18) ? ow2[(o * 32 + c) * 9 + k] : 0.0f;
}

// tiled transpose: fw1 [128][12544] -> g_fw1T [12544][128], both sides coalesced
__global__ void prep_fw1T(const float* __restrict__ fw1) {
    __shared__ float tile[32][33];
    int k = blockIdx.x * 32 + threadIdx.x;
    int n = blockIdx.y * 32 + threadIdx.y;
    tile[threadIdx.y][threadIdx.x] = fw1[n * 12544 + k];
    __syncthreads();
    int k2 = blockIdx.x * 32 + threadIdx.y;
    int n2 = blockIdx.y * 32 + threadIdx.x;
    g_fw1T[k2 * 128 + n2] = tile[threadIdx.x][threadIdx.y];
}

// ---------------- stage 1: conv1(offsets) + deform1 + relu + pool2x2 ------
__device__ __forceinline__ float samp28(const float* sx, int y, int x) {
    return (y >= 0 && y < 28 && x >= 0 && x < 28) ? sx[y * 28 + x] : 0.0f;
}

__global__ __launch_bounds__(784) void kA(
    const float* __restrict__ x,  const float* __restrict__ ow1,
    const float* __restrict__ ob1, const float* __restrict__ w1,
    const float* __restrict__ b1)
{
    __shared__ __align__(16) float sx[784];
    __shared__ __align__(16) float ss[9 * 784];    // bilinear samples [k][p28]
    __shared__ __align__(16) float sow1T[162];     // [k][o]
    __shared__ __align__(16) float sw1T[288];      // [k][c]
    __shared__ __align__(16) float sob1[18];
    __shared__ __align__(16) float sb1[32];
    int b = blockIdx.x, t = threadIdx.x;

    sx[t] = x[b * 784 + t];
    if (t < 162) { int o = t % 18, k = t / 18; sow1T[t] = ow1[o * 9 + k]; }
    if (t < 288) { int c = t % 32, k = t / 32; sw1T[t] = w1[c * 9 + k]; }
    if (t < 18) sob1[t] = ob1[t];
    if (t < 32) sb1[t] = b1[t];
    __syncthreads();

    // phase 1: one thread per 28x28 pixel — offset conv (1->18) + bilinear
    {
        int y = t / 28, xx = t % 28;
        ull off9[9];
        const ull* bb = (const ull*)sob1;
#pragma unroll
        for (int j = 0; j < 9; j++) off9[j] = bb[j];
#pragma unroll
        for (int ky = 0; ky < 3; ky++)
#pragma unroll
            for (int kx = 0; kx < 3; kx++) {
                float xv = samp28(sx, y - 1 + ky, xx - 1 + kx);
                ull xs = splat2(xv);
                const ull* wp = (const ull*)sow1T + (ky * 3 + kx) * 9;
#pragma unroll
                for (int j = 0; j < 9; j++) off9[j] = ffma2(xs, wp[j], off9[j]);
            }
#pragma unroll
        for (int k = 0; k < 9; k++) {
            float2 d = f2unpack(off9[k]);
            float py = d.x + (float)(y  - 1 + k / 3);
            float px = d.y + (float)(xx - 1 + k % 3);
            float y0f = floorf(py), x0f = floorf(px);
            int y0 = (int)y0f, x0i = (int)x0f;
            float wy1 = py - y0f, wx1 = px - x0f;
            float wy0 = 1.0f - wy1, wx0 = 1.0f - wx1;
            float v00 = samp28(sx, y0,     x0i    );
            float v01 = samp28(sx, y0,     x0i + 1);
            float v10 = samp28(sx, y0 + 1, x0i    );
            float v11 = samp28(sx, y0 + 1, x0i + 1);
            ss[k * 784 + t] = v00 * wy0 * wx0 + v01 * wy0 * wx1
                            + v10 * wy1 * wx0 + v11 * wy1 * wx1;
        }
    }
    __syncthreads();

    // phase 2: 4 groups x 8 channels, relu + 2x2 pool
    {
        int p = t % 196, g = t / 196;
        int oy = p / 14, ox = p % 14;
        float pool[8];
#pragma unroll
        for (int j = 0; j < 8; j++) pool[j] = 0.0f;
        const ull* bp = (const ull*)(sb1 + g * 8);
#pragma unroll
        for (int sub = 0; sub < 4; sub++) {
            int yy = oy * 2 + (sub >> 1);
            int xx = ox * 2 + (sub & 1);
            int pp = yy * 28 + xx;
            ull o4[4];
#pragma unroll
            for (int j = 0; j < 4; j++) o4[j] = bp[j];
#pragma unroll
            for (int k = 0; k < 9; k++) {
                ull vs = splat2(ss[k * 784 + pp]);
                const ull* wp = (const ull*)sw1T + k * 16 + g * 4;
                o4[0] = ffma2(vs, wp[0], o4[0]);
                o4[1] = ffma2(vs, wp[1], o4[1]);
                o4[2] = ffma2(vs, wp[2], o4[2]);
                o4[3] = ffma2(vs, wp[3], o4[3]);
            }
#pragma unroll
            for (int j = 0; j < 4; j++) {
                float2 u = f2unpack(o4[j]);
                pool[2 * j]     += fmaxf(u.x, 0.0f);
                pool[2 * j + 1] += fmaxf(u.y, 0.0f);
            }
        }
#pragma unroll
        for (int j = 0; j < 8; j++)
            g_h1p[(b * 32 + g * 8 + j) * 196 + p] = pool[j] * 0.25f;
    }
}

// ---------------- stage 2: conv2(offsets) + deform2 + relu -----------------
// 784 threads: 4 groups x (16 output channels | 8 input-channel slice).
// dynamic smem: sh[6272] | sv[6272] (ow2r, then gather buffer) | sw2[18432] | sbuf[14112]
__global__ __launch_bounds__(784) void kB(
    const float* __restrict__ ob2, const float* __restrict__ b2)
{
    extern __shared__ float smem[];
    float*    sh   = smem;            // 32*196 activations [c][p]
    float*    sv   = smem + 6272;     // ow2r (phase 2), gather v[c][p] (phase 4)
    float*    sw2  = smem + 12544;    // w2r [k][c][co]
    float*    sbuf = smem + 30976;    // offset partials -> coefs
    unsigned* sidx = (unsigned*)(smem + 30976) + 7056;  // packed tap indices
    __shared__ __align__(16) float sob2s[18];
    __shared__ __align__(16) float sb2s[64];

    int b = blockIdx.x, t = threadIdx.x;
    for (int i = t; i < 6272;  i += 784) sh[i]  = g_h1p[b * 6272 + i];
    for (int i = t; i < 5760;  i += 784) sv[i]  = g_ow2r[i];
    for (int i = t; i < 18432; i += 784) sw2[i] = g_w2r[i];
    if (t < 18) sob2s[t] = ob2[t];
    if (t < 64) sb2s[t]  = b2[t];
    __syncthreads();

    int g = t / 196, p = t % 196;
    int y = p / 14,  x = p % 14;

    // phase 2: partial offset conv (each group covers 8 input channels)
    {
        ull a9[9];
        if (g == 0) {
            const ull* bb = (const ull*)sob2s;
#pragma unroll
            for (int j = 0; j < 9; j++) a9[j] = bb[j];
        } else {
#pragma unroll
            for (int j = 0; j < 9; j++) a9[j] = 0ull;
        }
#pragma unroll
        for (int ky = 0; ky < 3; ky++)
#pragma unroll
            for (int kx = 0; kx < 3; kx++) {
                int yy = y - 1 + ky, xc = x - 1 + kx;
                if (yy >= 0 && yy < 14 && xc >= 0 && xc < 14) {
                    int p2 = yy * 14 + xc, kk = ky * 3 + kx;
                    const float* shb = sh + g * 8 * 196 + p2;
                    const ull* ow = (const ull*)sv + (kk * 32 + g * 8) * 10;
#pragma unroll
                    for (int cj = 0; cj < 8; cj++) {
                        ull hs = splat2(shb[cj * 196]);
                        const ull* wp = ow + cj * 10;
#pragma unroll
                        for (int j = 0; j < 9; j++) a9[j] = ffma2(hs, wp[j], a9[j]);
                    }
                }
            }
        float* dst = sbuf + (g * 196 + p) * 18;
#pragma unroll
        for (int j = 0; j < 9; j++) {
            float2 u = f2unpack(a9[j]);
            dst[2 * j] = u.x; dst[2 * j + 1] = u.y;
        }
    }
    __syncthreads();

    // phase 3: reduce partials, compute bilinear coefs + packed indices
    float offv[18];
    if (t < 196) {
#pragma unroll
        for (int o = 0; o < 18; o++)
            offv[o] = sbuf[t * 18 + o] + sbuf[(196 + t) * 18 + o]
                    + sbuf[(392 + t) * 18 + o] + sbuf[(588 + t) * 18 + o];
    }
    __syncthreads();
    if (t < 196) {
#pragma unroll
        for (int k = 0; k < 9; k++) {
            float py = offv[2 * k]     + (float)(y - 1 + k / 3);
            float px = offv[2 * k + 1] + (float)(x - 1 + k % 3);
            float y0f = floorf(py), x0f = floorf(px);
            int y0 = (int)y0f, x0i = (int)x0f;
            float wy1 = py - y0f, wx1 = px - x0f;
            float wy0 = 1.0f - wy1, wx0 = 1.0f - wx1;
            bool by0 = (y0 >= 0) && (y0 < 14);
            bool by1 = (y0 + 1 >= 0) && (y0 + 1 < 14);
            bool bx0 = (x0i >= 0) && (x0i < 14);
            bool bx1 = (x0i + 1 >= 0) && (x0i + 1 < 14);
            float c00 = (by0 && bx0) ? wy0 * wx0 : 0.0f;
            float c01 = (by0 && bx1) ? wy0 * wx1 : 0.0f;
            float c10 = (by1 && bx0) ? wy1 * wx0 : 0.0f;
            float c11 = (by1 && bx1) ? wy1 * wx1 : 0.0f;
            unsigned i00 = (by0 && bx0) ? (unsigned)(y0 * 14 + x0i)           : 0u;
            unsigned i01 = (by0 && bx1) ? (unsigned)(y0 * 14 + x0i + 1)       : 0u;
            unsigned i10 = (by1 && bx0) ? (unsigned)((y0 + 1) * 14 + x0i)     : 0u;
            unsigned i11 = (by1 && bx1) ? (unsigned)((y0 + 1) * 14 + x0i + 1) : 0u;
            sbuf[(k * 4 + 0) * 196 + t] = c00;
            sbuf[(k * 4 + 1) * 196 + t] = c01;
            sbuf[(k * 4 + 2) * 196 + t] = c10;
            sbuf[(k * 4 + 3) * 196 + t] = c11;
            sidx[k * 196 + t] = i00 | (i01 << 8) | (i10 << 16) | (i11 << 24);
        }
    }
    __syncthreads();

    // phase 4: per-k shared gather, then 16-channel FFMA2 accumulation
    ull acc[8];
    {
        const ull* bp = (const ull*)(sb2s + g * 16);
#pragma unroll
        for (int j = 0; j < 8; j++) acc[j] = bp[j];
    }
    for (int k = 0; k < 9; k++) {
        unsigned ip = sidx[k * 196 + p];
        float c0 = sbuf[(k * 4 + 0) * 196 + p];
        float c1 = sbuf[(k * 4 + 1) * 196 + p];
        float c2 = sbuf[(k * 4 + 2) * 196 + p];
        float c3 = sbuf[(k * 4 + 3) * 196 + p];
        int i00 = ip & 255, i01 = (ip >> 8) & 255;
        int i10 = (ip >> 16) & 255, i11 = ip >> 24;
#pragma unroll
        for (int j = 0; j < 8; j++) {
            const float* base = sh + (g * 8 + j) * 196;
            sv[(g * 8 + j) * 196 + p] =
                c0 * base[i00] + c1 * base[i01] + c2 * base[i10] + c3 * base[i11];
        }
        __syncthreads();
        const float* wk = sw2 + k * 2048 + g * 16;
#pragma unroll 4
        for (int c = 0; c < 32; c++) {
            ull vs = splat2(sv[c * 196 + p]);
            const ulonglong2* wp = (const ulonglong2*)(wk + c * 64);
            ulonglong2 wa = wp[0], wb = wp[1], wc = wp[2], wd = wp[3];
            acc[0] = ffma2(vs, wa.x, acc[0]); acc[1] = ffma2(vs, wa.y, acc[1]);
            acc[2] = ffma2(vs, wb.x, acc[2]); acc[3] = ffma2(vs, wb.y, acc[3]);
            acc[4] = ffma2(vs, wc.x, acc[4]); acc[5] = ffma2(vs, wc.y, acc[5]);
            acc[6] = ffma2(vs, wd.x, acc[6]); acc[7] = ffma2(vs, wd.y, acc[7]);
        }
        __syncthreads();
    }
#pragma unroll
    for (int j = 0; j < 8; j++) {
        float2 u = f2unpack(acc[j]);
        g_h2[(b * 64 + g * 16 + 2 * j    ) * 196 + p] = fmaxf(u.x, 0.0f);
        g_h2[(b * 64 + g * 16 + 2 * j + 1) * 196 + p] = fmaxf(u.y, 0.0f);
    }
}

// ---------------- FC1: split-K GEMM (M=1024, N=128, K=12544) ---------------
// BM=64, BN=128, BK=16, splitK=16, 256 threads/block.
// Thread tile 8m x 4n. A tile stored k-major (padded row 72) so each warp
// reads its m-pairs with two broadcast LDS.128. B stored plain float; the 4
// n-values are splatted in registers (halves B LDS bytes vs splatted smem).
__global__ __launch_bounds__(256) void kC_gemm() {
    __shared__ __align__(16) float As[16][72];   // [k][m], padded
    __shared__ __align__(16) float Bs[16][128];  // [k][n]
    int tid = threadIdx.x;
    int m0 = blockIdx.x * 64;
    int kbase = blockIdx.y * 784;

    ull acc[4][4];   // 4 m-pairs x 4 n
#pragma unroll
    for (int i = 0; i < 4; i++)
#pragma unroll
        for (int j = 0; j < 4; j++) acc[i][j] = 0ull;

    int ar  = tid / 4;            // A row 0..63
    int ac  = (tid % 4) * 4;      // A k-quad
    int brr = tid / 16;           // B k-row 0..15
    int bn  = (tid % 16) * 8;     // B n-octet
    int m_base = (tid >> 5) * 8;  // warp-uniform: 0..56
    int n_base = (tid & 31) * 4;  // 0..124

    const float* Ag = g_h2 + (m0 + ar) * 12544 + kbase + ac;
    const float* Bg = g_fw1T + (kbase + brr) * 128 + bn;

    for (int it = 0; it < 49; it++) {
        // load A (64x16) transposed into As[k][m]
        float4 av = *(const float4*)(Ag + it * 16);
        As[ac + 0][ar] = av.x; As[ac + 1][ar] = av.y;
        As[ac + 2][ar] = av.z; As[ac + 3][ar] = av.w;
        // load B (16x128)
        const float* bg = Bg + it * 16 * 128;
        float4 b0 = *(const float4*)(bg);
        float4 b1 = *(const float4*)(bg + 4);
        *(float4*)(&Bs[brr][bn])     = b0;
        *(float4*)(&Bs[brr][bn + 4]) = b1;
        __syncthreads();
#pragma unroll
        for (int k = 0; k < 16; k++) {
            // warp-uniform m-pairs (broadcast LDS.128)
            ulonglong2 a01 = *(const ulonglong2*)(&As[k][m_base]);
            ulonglong2 a23 = *(const ulonglong2*)(&As[k][m_base + 4]);
            float4 bv = *(const float4*)(&Bs[k][n_base]);
            ull s0 = splat2(bv.x), s1 = splat2(bv.y);
            ull s2 = splat2(bv.z), s3 = splat2(bv.w);
            acc[0][0] = ffma2(a01.x, s0, acc[0][0]);
            acc[0][1] = ffma2(a01.x, s1, acc[0][1]);
            acc[0][2] = ffma2(a01.x, s2, acc[0][2]);
            acc[0][3] = ffma2(a01.x, s3, acc[0][3]);
            acc[1][0] = ffma2(a01.y, s0, acc[1][0]);
            acc[1][1] = ffma2(a01.y, s1, acc[1][1]);
            acc[1][2] = ffma2(a01.y, s2, acc[1][2]);
            acc[1][3] = ffma2(a01.y, s3, acc[1][3]);
            acc[2][0] = ffma2(a23.x, s0, acc[2][0]);
            acc[2][1] = ffma2(a23.x, s1, acc[2][1]);
            acc[2][2] = ffma2(a23.x, s2, acc[2][2]);
            acc[2][3] = ffma2(a23.x, s3, acc[2][3]);
            acc[3][0] = ffma2(a23.y, s0, acc[3][0]);
            acc[3][1] = ffma2(a23.y, s1, acc[3][1]);
            acc[3][2] = ffma2(a23.y, s2, acc[3][2]);
            acc[3][3] = ffma2(a23.y, s3, acc[3][3]);
        }
        __syncthreads();
    }
    float* dst = g_fc1part + blockIdx.y * 131072;
#pragma unroll
    for (int mp = 0; mp < 4; mp++) {
        int r0 = (m0 + m_base + 2 * mp) * 128 + n_base;
#pragma unroll
        for (int j = 0; j < 4; j++) {
            float2 u = f2unpack(acc[mp][j]);
            dst[r0 + j]       = u.x;
            dst[r0 + 128 + j] = u.y;
        }
    }
}

__global__ void kE_reduce(const float* __restrict__ fb1) {
    int id = blockIdx.x * blockDim.x + threadIdx.x;  // 131072
    if (id >= 131072) return;
    int n = id % 128;
    float s = fb1[n];
#pragma unroll
    for (int zz = 0; zz < 16; zz++) s += g_fc1part[zz * 131072 + id];
    g_h3[id] = fmaxf(s, 0.0f);
}

// ---------------- FC2 ------------------------------------------------------
__global__ void kF_fc2(const float* __restrict__ fw2, const float* __restrict__ fb2,
                       float* __restrict__ out) {
    int id = blockIdx.x * blockDim.x + threadIdx.x;  // 10240
    if (id >= 10240) return;
    int m = id / 10, n = id % 10;
    float s = fb2[n];
    const float* hrow = g_h3 + m * 128;
    const float* wrow = fw2 + n * 128;
#pragma unroll 8
    for (int j = 0; j < 128; j++) s += hrow[j] * wrow[j];
    out[id] = s;
}

// ---------------- launch ---------------------------------------------------
extern "C" void kernel_launch(void* const* d_in, const int* in_sizes, int n_in,
                              void* d_out, int out_size) {
    const float* x   = (const float*)d_in[0];
    const float* ow1 = (const float*)d_in[1];
    const float* ob1 = (const float*)d_in[2];
    const float* w1  = (const float*)d_in[3];
    const float* b1  = (const float*)d_in[4];
    const float* ow2 = (const float*)d_in[5];
    const float* ob2 = (const float*)d_in[6];
    const float* w2  = (const float*)d_in[7];
    const float* b2  = (const float*)d_in[8];
    const float* fw1 = (const float*)d_in[9];
    const float* fb1 = (const float*)d_in[10];
    const float* fw2 = (const float*)d_in[11];
    const float* fb2 = (const float*)d_in[12];
    float* out = (float*)d_out;

    prep_w2r <<<(18432 + 255) / 256, 256>>>(w2);
    prep_ow2r<<<(5760  + 255) / 256, 256>>>(ow2);
    {
        dim3 tg(392, 4);
        dim3 tb(32, 32);
        prep_fw1T<<<tg, tb>>>(fw1);
    }

    kA<<<1024, 784>>>(x, ow1, ob1, w1, b1);

    const int KB_SMEM = 45088 * 4;   // 180352 bytes
    cudaFuncSetAttribute(kB, cudaFuncAttributeMaxDynamicSharedMemorySize, KB_SMEM);
    kB<<<1024, 784, KB_SMEM>>>(ob2, b2);

    dim3 gg(16, 16);
    kC_gemm<<<gg, 256>>>();
    kE_reduce<<<(131072 + 255) / 256, 256>>>(fb1);
    kF_fc2<<<(10240 + 255) / 256, 256>>>(fw2, fb2, out);
}